// round 14
// baseline (speedup 1.0000x reference)
#include <cuda_runtime.h>
#include <cuda_fp16.h>
#include <math.h>
#include <stdint.h>

#define SEQ 2048
#define DMODEL 2048
#define NH 16
#define DH 128
#define DFF 8192
#define BOTTLE 1088   /* BACKGROUND_LEN + STYLE_VECS_LEN */
#define BG 1024       /* BACKGROUND_LEN */

// -------- scratch (no allocations allowed) --------
__device__ __half g_xnh[(size_t)SEQ * DMODEL];
__device__ __half g_qkvh[(size_t)SEQ * 3 * DMODEL];
__device__ __half g_atth[(size_t)SEQ * DMODEL];
__device__ __half g_ffh[(size_t)SEQ * DFF];
// half weights, NATURAL [K, N] layouts (qkv fused along N)
__device__ __half g_wqkvh[(size_t)DMODEL * 3 * DMODEL];
__device__ __half g_woh[(size_t)DMODEL * DMODEL];
__device__ __half g_w1h[(size_t)DMODEL * DFF];
__device__ __half g_w2h[(size_t)DFF * DMODEL];

// -------- fp16 mma + ldmatrix --------
__device__ __forceinline__ void mma_f16(float c[4], const uint32_t a[4], const uint32_t b0,
                                        const uint32_t b1) {
    asm volatile(
        "mma.sync.aligned.m16n8k16.row.col.f32.f16.f16.f32 "
        "{%0,%1,%2,%3}, {%4,%5,%6,%7}, {%8,%9}, {%0,%1,%2,%3};\n"
        : "+f"(c[0]), "+f"(c[1]), "+f"(c[2]), "+f"(c[3])
        : "r"(a[0]), "r"(a[1]), "r"(a[2]), "r"(a[3]), "r"(b0), "r"(b1));
}
__device__ __forceinline__ void ldsm4(uint32_t* r, uint32_t addr) {
    asm volatile("ldmatrix.sync.aligned.m8n8.x4.shared.b16 {%0,%1,%2,%3}, [%4];"
                 : "=r"(r[0]), "=r"(r[1]), "=r"(r[2]), "=r"(r[3]) : "r"(addr));
}
__device__ __forceinline__ void ldsm4t(uint32_t* r, uint32_t addr) {
    asm volatile("ldmatrix.sync.aligned.m8n8.x4.trans.shared.b16 {%0,%1,%2,%3}, [%4];"
                 : "=r"(r[0]), "=r"(r[1]), "=r"(r[2]), "=r"(r[3]) : "r"(addr));
}
// pack two fp32 -> one fp16x2 register (lo = a, hi = b)
__device__ __forceinline__ uint32_t packh2(float a, float b) {
    uint32_t r;
    asm("cvt.rn.f16x2.f32 %0, %2, %1;" : "=r"(r) : "f"(a), "f"(b));
    return r;
}

// -------- cp.async helpers --------
__device__ __forceinline__ void cp16(uint32_t s, const void* g) {
    asm volatile("cp.async.cg.shared.global [%0], [%1], 16;" :: "r"(s), "l"(g));
}
__device__ __forceinline__ void cp_commit() { asm volatile("cp.async.commit_group;"); }
template <int N> __device__ __forceinline__ void cp_wait() {
    asm volatile("cp.async.wait_group %0;" :: "n"(N));
}

// -------- reductions --------
__device__ __forceinline__ float blockReduceSum(float val) {
    __shared__ float sh[8];
    __shared__ float res;
    int lane = threadIdx.x & 31, w = threadIdx.x >> 5;
    #pragma unroll
    for (int o = 16; o > 0; o >>= 1) val += __shfl_xor_sync(0xffffffffu, val, o);
    if (lane == 0) sh[w] = val;
    __syncthreads();
    if (threadIdx.x == 0) {
        float s = 0.f;
        #pragma unroll
        for (int i = 0; i < 8; i++) s += sh[i];
        res = s;
    }
    __syncthreads();
    float r = res;
    __syncthreads();
    return r;
}

// -------- streaming fp32 -> fp16 convert with column placement --------
// N4 is a power of two; sh = log2(N4).
__global__ void cvt_h_kernel(const float4* __restrict__ in, __half* __restrict__ out,
                             int sh, int ldo, int off, int total4) {
    int i = blockIdx.x * blockDim.x + threadIdx.x;
    if (i >= total4) return;
    int row = i >> sh, c4 = i & ((1 << sh) - 1);
    float4 v = in[i];
    uint2 o;
    o.x = packh2(v.x, v.y);
    o.y = packh2(v.z, v.w);
    *(uint2*)(out + (size_t)row * ldo + off + c4 * 4) = o;
}

// -------- LayerNorm (half output) --------
__global__ void ln_kernel(const float* __restrict__ x, const float* __restrict__ sc,
                          const float* __restrict__ of, __half* __restrict__ out) {
    int row = blockIdx.x;
    const float* xr = x + (size_t)row * DMODEL;
    __half* o = out + (size_t)row * DMODEL;
    float s = 0.f, s2 = 0.f;
    for (int i = threadIdx.x; i < DMODEL; i += blockDim.x) {
        float v = xr[i];
        s += v; s2 += v * v;
    }
    s  = blockReduceSum(s);
    s2 = blockReduceSum(s2);
    float mean = s / DMODEL;
    float var  = s2 / DMODEL - mean * mean;
    float r = rsqrtf(var + 1e-5f);
    for (int i = threadIdx.x; i < DMODEL; i += blockDim.x)
        o[i] = __float2half_rn(sc[i] * r * (xr[i] - mean) + of[i]);
}

// -------- RoPE on packed half qkv (q at 0, k at DMODEL) --------
__global__ void rope_kernel(__half* __restrict__ qkv) {
    int idx = blockIdx.x * blockDim.x + threadIdx.x;
    if (idx >= SEQ * (DMODEL / 2)) return;
    int t = idx / (DMODEL / 2);
    int r = idx % (DMODEL / 2);
    int h = r / (DH / 2);
    int i = r % (DH / 2);
    float inv = powf(10000.0f, -(float)(2 * i) / (float)DH);
    float ang = (float)t * inv;
    float s, c;
    sincosf(ang, &s, &c);
    size_t base = (size_t)t * (3 * DMODEL) + (size_t)h * DH + 2 * i;
    __half2* qp = (__half2*)(qkv + base);
    float2 q = __half22float2(*qp);
    *qp = __floats2half2_rn(q.x * c - q.y * s, q.y * c + q.x * s);
    __half2* kp = (__half2*)(qkv + base + DMODEL);
    float2 k = __half22float2(*kp);
    *kp = __floats2half2_rn(k.x * c - k.y * s, k.y * c + k.x * s);
}

__device__ __forceinline__ float gelu_f(float x) {
    float x3 = x * x * x;
    return 0.5f * x * (1.0f + tanhf(0.7978845608028654f * (x + 0.044715f * x3)));
}

// ============ FP16 tensor-core GEMM, 128x256 CTA tile, B natural [K,N] ============
// 8 warps as 2(m) x 4(n); warp tile 64x64. BK=32, 3-stage cp.async.
// EPI 0: v = acc   EPI 1: v = gelu(acc + bias[n])   EPI 2: v = C[idx] + acc + bias[n]
// OUTH: write half to Ch.
template <int EPI, int OUTH>
__global__ __launch_bounds__(256, 1)
void hgemm(const __half* __restrict__ A, const __half* __restrict__ B,
           const float* __restrict__ bias, float* __restrict__ C,
           __half* __restrict__ Ch, int K, int ldb, int ldc) {
    constexpr int S = 3, BK = 32;
    constexpr int LDA = 40;                  // A smem row halves (pad 8)
    constexpr int LDB = 264;                 // B smem row halves (pad 8)
    constexpr int ASTAGE = 128 * LDA;        // 5120 halves
    constexpr int BSTAGE = BK * LDB;         // 8448 halves

    extern __shared__ __half smh[];
    __half* Asm = smh;
    __half* Bsm = smh + S * ASTAGE;

    int t = threadIdx.x;
    int m0 = blockIdx.y * 128, n0 = blockIdx.x * 256;
    int lane = t & 31, warp = t >> 5;
    int wm = (warp >> 2) * 64;    // 0 / 64
    int wn = (warp & 3) * 64;     // 0,64,128,192
    int gid = lane >> 2, t4 = lane & 3;

    float acc[4][8][4];
    #pragma unroll
    for (int f = 0; f < 4; f++)
        #pragma unroll
        for (int g = 0; g < 8; g++)
            #pragma unroll
            for (int e = 0; e < 4; e++) acc[f][g][e] = 0.f;

    uint32_t aBase = (uint32_t)__cvta_generic_to_shared(Asm);
    uint32_t bBase = (uint32_t)__cvta_generic_to_shared(Bsm);

    int nt = K / BK;

    // A stage: 128 x 32 halves = 512 chunks (2/thread); B stage: 32 x 256 = 1024 chunks (4/thread)
    auto load_stage = [&](int s, int kt) {
        int k0 = kt * BK;
        uint32_t as = aBase + s * ASTAGE * 2;
        uint32_t bs = bBase + s * BSTAGE * 2;
        #pragma unroll
        for (int i = 0; i < 2; i++) {
            int cid = t + i * 256;
            int row = cid >> 2, c = (cid & 3) * 8;
            cp16(as + (row * LDA + c) * 2, A + (size_t)(m0 + row) * K + k0 + c);
        }
        #pragma unroll
        for (int i = 0; i < 4; i++) {
            int cid = t + i * 256;
            int row = cid >> 5, c = (cid & 31) * 8;
            cp16(bs + (row * LDB + c) * 2, B + (size_t)(k0 + row) * ldb + n0 + c);
        }
    };

    #pragma unroll
    for (int s = 0; s < S - 1; s++) {
        if (s < nt) load_stage(s, s);
        cp_commit();
    }

    int lrow = (lane & 7) + ((lane >> 3) & 1) * 8;   // A ldsm row
    int lcol = (lane >> 4) * 8;                      // A ldsm k-offset
    int vrow = lane & 15, vcol = (lane >> 4) * 8;    // B trans-ldsm row/col

    int stg = 0;
    for (int kt = 0; kt < nt; kt++) {
        cp_wait<S - 2>();
        __syncthreads();
        int nx = kt + S - 1;
        if (nx < nt) load_stage((stg + S - 1) % S, nx);
        cp_commit();

        uint32_t as = aBase + stg * ASTAGE * 2;
        uint32_t bs = bBase + stg * BSTAGE * 2;

        #pragma unroll
        for (int kk = 0; kk < BK; kk += 16) {
            uint32_t af[4][4];
            #pragma unroll
            for (int f = 0; f < 4; f++)
                ldsm4(af[f], as + ((wm + f * 16 + lrow) * LDA + kk + lcol) * 2);
            uint32_t bf[4][4];
            #pragma unroll
            for (int g2 = 0; g2 < 4; g2++)
                ldsm4t(bf[g2], bs + ((kk + vrow) * LDB + wn + g2 * 16 + vcol) * 2);
            #pragma unroll
            for (int f = 0; f < 4; f++)
                #pragma unroll
                for (int g2 = 0; g2 < 4; g2++) {
                    mma_f16(acc[f][2 * g2 + 0], af[f], bf[g2][0], bf[g2][1]);
                    mma_f16(acc[f][2 * g2 + 1], af[f], bf[g2][2], bf[g2][3]);
                }
        }
        stg = (stg + 1) % S;
    }

    #pragma unroll
    for (int f = 0; f < 4; f++) {
        #pragma unroll
        for (int g = 0; g < 8; g++) {
            #pragma unroll
            for (int half = 0; half < 2; half++) {
                int m = m0 + wm + f * 16 + gid + half * 8;
                int n = n0 + wn + g * 8 + 2 * t4;
                float v0 = acc[f][g][half * 2 + 0];
                float v1 = acc[f][g][half * 2 + 1];
                size_t idx = (size_t)m * ldc + n;
                if (EPI == 1) {
                    v0 = gelu_f(v0 + bias[n]);
                    v1 = gelu_f(v1 + bias[n + 1]);
                } else if (EPI == 2) {
                    v0 = C[idx]     + v0 + bias[n];
                    v1 = C[idx + 1] + v1 + bias[n + 1];
                }
                if (OUTH) {
                    *(uint32_t*)(Ch + idx) = packh2(v0, v1);
                } else {
                    C[idx]     = v0;
                    C[idx + 1] = v1;
                }
            }
        }
    }
}

// ============ FP16 flash attention (m16n8k16 mma, ldmatrix, online softmax) ============
__global__ void __launch_bounds__(256, 1)
flash_kernel(const __half* __restrict__ qkv, const float* __restrict__ bias,
             __half* __restrict__ att) {
    constexpr int LD = 3 * DMODEL;
    constexpr int STR = 136;
    extern __shared__ __half smh[];
    __half* Qs = smh;
    __half* Ks = smh + 128 * STR;
    __half* Vs = smh + 2 * 128 * STR;
    uint32_t qB = (uint32_t)__cvta_generic_to_shared(Qs);
    uint32_t kB = (uint32_t)__cvta_generic_to_shared(Ks);
    uint32_t vB = (uint32_t)__cvta_generic_to_shared(Vs);

    int mb = blockIdx.x, h = blockIdx.y;
    int m0 = mb * 128;
    int t = threadIdx.x, lane = t & 31, warp = t >> 5;
    int gid = lane >> 2, t4 = lane & 3;
    int wrow = warp * 16;

    const __half* kbase = qkv + DMODEL + h * DH;
    const __half* vbase = qkv + 2 * DMODEL + h * DH;

    int lr = t >> 1, lc = (t & 1) * 64;

    int it0 = (m0 >= 1152) ? 8 : 0;
    {
        const __half* g = qkv + (size_t)(m0 + lr) * LD + h * DH + lc;
        uint32_t s = qB + (lr * STR + lc) * 2;
        #pragma unroll
        for (int i = 0; i < 8; i++) cp16(s + i * 16, g + i * 8);
    }
    {
        const __half* g = kbase + (size_t)(it0 * 128 + lr) * LD + lc;
        uint32_t s = kB + (lr * STR + lc) * 2;
        #pragma unroll
        for (int i = 0; i < 8; i++) cp16(s + i * 16, g + i * 8);
    }
    cp_commit();
    cp_wait<0>();
    __syncthreads();

    float o[16][4];
    #pragma unroll
    for (int g = 0; g < 16; g++) { o[g][0] = o[g][1] = o[g][2] = o[g][3] = 0.f; }
    float mrow0 = -INFINITY, mrow1 = -INFINITY;
    float lsum0 = 0.f, lsum1 = 0.f;

    const float scale = 0.08838834764831845f;
    int me0 = m0 + wrow + gid;
    int me1 = me0 + 8;

    int lrow = (lane & 7) + ((lane >> 3) & 1) * 8;
    int lcol = (lane >> 4) * 8;
    int vrow = lane & 15, vcol = (lane >> 4) * 8;

    for (int it = it0; it <= mb; it++) {
        int n0 = it * 128;

        {
            const __half* g = vbase + (size_t)(n0 + lr) * LD + lc;
            uint32_t s = vB + (lr * STR + lc) * 2;
            #pragma unroll
            for (int i = 0; i < 8; i++) cp16(s + i * 16, g + i * 8);
            cp_commit();
        }

        float s[16][4];
        #pragma unroll
        for (int g = 0; g < 16; g++) s[g][0] = s[g][1] = s[g][2] = s[g][3] = 0.f;

        #pragma unroll
        for (int kk = 0; kk < DH; kk += 16) {
            uint32_t af[4];
            ldsm4(af, qB + ((wrow + lrow) * STR + kk + lcol) * 2);
            #pragma unroll
            for (int g2 = 0; g2 < 8; g2++) {
                uint32_t bf[4];
                ldsm4(bf, kB + ((g2 * 16 + lrow) * STR + kk + lcol) * 2);
                mma_f16(s[2 * g2 + 0], af, bf[0], bf[2]);
                mma_f16(s[2 * g2 + 1], af, bf[1], bf[3]);
            }
        }
        __syncthreads();

        if (it < mb) {
            const __half* g = kbase + (size_t)(n0 + 128 + lr) * LD + lc;
            uint32_t sa = kB + (lr * STR + lc) * 2;
            #pragma unroll
            for (int i = 0; i < 8; i++) cp16(sa + i * 16, g + i * 8);
        }
        cp_commit();

        float mx0 = -INFINITY, mx1 = -INFINITY;
        const float* bp0 = bias + (size_t)me0 * SEQ + n0 + 2 * t4;
        const float* bp1 = bias + (size_t)me1 * SEQ + n0 + 2 * t4;
        #pragma unroll
        for (int g = 0; g < 16; g++) {
            int nc = n0 + g * 8 + 2 * t4;
            float2 b0 = *(const float2*)(bp0 + g * 8);
            float2 b1 = *(const float2*)(bp1 + g * 8);
            bool a00 = (nc     <= me0) && !((me0 >= BOTTLE) && (nc     < BG));
            bool a01 = (nc + 1 <= me0) && !((me0 >= BOTTLE) && (nc + 1 < BG));
            bool a10 = (nc     <= me1) && !((me1 >= BOTTLE) && (nc     < BG));
            bool a11 = (nc + 1 <= me1) && !((me1 >= BOTTLE) && (nc + 1 < BG));
            s[g][0] = s[g][0] * scale + (a00 ? 0.f : -1e10f) + b0.x;
            s[g][1] = s[g][1] * scale + (a01 ? 0.f : -1e10f) + b0.y;
            s[g][2] = s[g][2] * scale + (a10 ? 0.f : -1e10f) + b1.x;
            s[g][3] = s[g][3] * scale + (a11 ? 0.f : -1e10f) + b1.y;
            mx0 = fmaxf(mx0, fmaxf(s[g][0], s[g][1]));
            mx1 = fmaxf(mx1, fmaxf(s[g][2], s[g][3]));
        }
        mx0 = fmaxf(mx0, __shfl_xor_sync(0xffffffffu, mx0, 1));
        mx0 = fmaxf(mx0, __shfl_xor_sync(0xffffffffu, mx0, 2));
        mx1 = fmaxf(mx1, __shfl_xor_sync(0xffffffffu, mx1, 1));
        mx1 = fmaxf(mx1, __shfl_xor_sync(0xffffffffu, mx1, 2));
        float mn0 = fmaxf(mrow0, mx0), mn1 = fmaxf(mrow1, mx1);
        float al0 = __expf(mrow0 - mn0), al1 = __expf(mrow1 - mn1);
        float rs0 = 0.f, rs1 = 0.f;
        #pragma unroll
        for (int g = 0; g < 16; g++) {
            s[g][0] = __expf(s[g][0] - mn0);
            s[g][1] = __expf(s[g][1] - mn0);
            s[g][2] = __expf(s[g][2] - mn1);
            s[g][3] = __expf(s[g][3] - mn1);
            rs0 += s[g][0] + s[g][1];
            rs1 += s[g][2] + s[g][3];
        }
        lsum0 = lsum0 * al0 + rs0;
        lsum1 = lsum1 * al1 + rs1;
        mrow0 = mn0; mrow1 = mn1;
        #pragma unroll
        for (int g = 0; g < 16; g++) {
            o[g][0] *= al0; o[g][1] *= al0; o[g][2] *= al1; o[g][3] *= al1;
        }

        cp_wait<1>();
        __syncthreads();

        #pragma unroll
        for (int kt = 0; kt < 8; kt++) {
            uint32_t a[4];
            a[0] = packh2(s[2 * kt][0],     s[2 * kt][1]);
            a[1] = packh2(s[2 * kt][2],     s[2 * kt][3]);
            a[2] = packh2(s[2 * kt + 1][0], s[2 * kt + 1][1]);
            a[3] = packh2(s[2 * kt + 1][2], s[2 * kt + 1][3]);
            #pragma unroll
            for (int nf2 = 0; nf2 < 8; nf2++) {
                uint32_t bf[4];
                ldsm4t(bf, vB + ((kt * 16 + vrow) * STR + nf2 * 16 + vcol) * 2);
                mma_f16(o[2 * nf2 + 0], a, bf[0], bf[1]);
                mma_f16(o[2 * nf2 + 1], a, bf[2], bf[3]);
            }
        }
        cp_wait<0>();
        __syncthreads();
    }

    lsum0 += __shfl_xor_sync(0xffffffffu, lsum0, 1);
    lsum0 += __shfl_xor_sync(0xffffffffu, lsum0, 2);
    lsum1 += __shfl_xor_sync(0xffffffffu, lsum1, 1);
    lsum1 += __shfl_xor_sync(0xffffffffu, lsum1, 2);
    float inv0 = 1.f / lsum0, inv1 = 1.f / lsum1;
    __half* o0 = att + (size_t)me0 * DMODEL + h * DH + 2 * t4;
    __half* o1 = att + (size_t)me1 * DMODEL + h * DH + 2 * t4;
    #pragma unroll
    for (int nf = 0; nf < 16; nf++) {
        *(uint32_t*)(o0 + nf * 8) = packh2(o[nf][0] * inv0, o[nf][1] * inv0);
        *(uint32_t*)(o1 + nf * 8) = packh2(o[nf][2] * inv1, o[nf][3] * inv1);
    }
}

extern "C" void kernel_launch(void* const* d_in, const int* in_sizes, int n_in,
                              void* d_out, int out_size) {
    (void)in_sizes; (void)n_in; (void)out_size;
    const float* x         = (const float*)d_in[0];
    const float* attn_bias = (const float*)d_in[1];
    const float* ln_scale  = (const float*)d_in[2];
    const float* ln_offset = (const float*)d_in[3];
    const float* Wq = (const float*)d_in[4];
    const float* Wk = (const float*)d_in[5];
    const float* Wv = (const float*)d_in[6];
    const float* Wo = (const float*)d_in[7];
    const float* W1 = (const float*)d_in[8];
    const float* b1 = (const float*)d_in[9];
    const float* W2 = (const float*)d_in[10];
    const float* b2 = (const float*)d_in[11];
    float* out = (float*)d_out;

    __half *xnh, *qkvh, *atth, *ffh, *wqkvh, *woh, *w1h, *w2h;
    cudaGetSymbolAddress((void**)&xnh,   g_xnh);
    cudaGetSymbolAddress((void**)&qkvh,  g_qkvh);
    cudaGetSymbolAddress((void**)&atth,  g_atth);
    cudaGetSymbolAddress((void**)&ffh,   g_ffh);
    cudaGetSymbolAddress((void**)&wqkvh, g_wqkvh);
    cudaGetSymbolAddress((void**)&woh,   g_woh);
    cudaGetSymbolAddress((void**)&w1h,   g_w1h);
    cudaGetSymbolAddress((void**)&w2h,   g_w2h);

    const int SM_HG = 3 * (128 * 40 + 32 * 264) * 2;   // 81408 B
    const int SM_FA = 3 * 128 * 136 * 2;                // 104448 B
    cudaFuncSetAttribute(hgemm<0, 1>, cudaFuncAttributeMaxDynamicSharedMemorySize, SM_HG);
    cudaFuncSetAttribute(hgemm<0, 0>, cudaFuncAttributeMaxDynamicSharedMemorySize, SM_HG);
    cudaFuncSetAttribute(hgemm<1, 1>, cudaFuncAttributeMaxDynamicSharedMemorySize, SM_HG);
    cudaFuncSetAttribute(hgemm<2, 0>, cudaFuncAttributeMaxDynamicSharedMemorySize, SM_HG);
    cudaFuncSetAttribute(flash_kernel, cudaFuncAttributeMaxDynamicSharedMemorySize, SM_FA);

    // 0. Streaming fp16 conversion of weights (natural [K,N] layout; qkv fused along N)
    {
        int thr = 256;
        int n4a = DMODEL * DMODEL / 4;
        int n4b = DMODEL * DFF / 4;
        cvt_h_kernel<<<(n4a + thr - 1) / thr, thr>>>((const float4*)Wq, wqkvh, 9,  3 * DMODEL, 0,          n4a);
        cvt_h_kernel<<<(n4a + thr - 1) / thr, thr>>>((const float4*)Wk, wqkvh, 9,  3 * DMODEL, DMODEL,     n4a);
        cvt_h_kernel<<<(n4a + thr - 1) / thr, thr>>>((const float4*)Wv, wqkvh, 9,  3 * DMODEL, 2 * DMODEL, n4a);
        cvt_h_kernel<<<(n4a + thr - 1) / thr, thr>>>((const float4*)Wo, woh, 9,  DMODEL, 0, n4a);
        cvt_h_kernel<<<(n4b + thr - 1) / thr, thr>>>((const float4*)W1, w1h, 11, DFF,    0, n4b);
        cvt_h_kernel<<<(n4b + thr - 1) / thr, thr>>>((const float4*)W2, w2h, 9,  DMODEL, 0, n4b);
    }

    // 1. LayerNorm -> xn half
    ln_kernel<<<SEQ, 256>>>(x, ln_scale, ln_offset, xnh);

    // 2. Fused QKV projection -> qkv half [SEQ, 6144]
    hgemm<0, 1><<<dim3(3 * DMODEL / 256, SEQ / 128), 256, SM_HG>>>(
        xnh, wqkvh, nullptr, nullptr, qkvh, DMODEL, 3 * DMODEL, 3 * DMODEL);

    // 3. RoPE (half, in place)
    rope_kernel<<<(SEQ * (DMODEL / 2) + 255) / 256, 256>>>(qkvh);

    // 4. FP16 flash attention -> att half
    flash_kernel<<<dim3(SEQ / 128, NH), 256, SM_FA>>>(qkvh, attn_bias, atth);

    // 5. attn_out = att @ Wo -> d_out (fp32)
    hgemm<0, 0><<<dim3(DMODEL / 256, SEQ / 128), 256, SM_HG>>>(
        atth, woh, nullptr, out, nullptr, DMODEL, DMODEL, DMODEL);

    // 6. ff = gelu(xn @ W1 + b1) -> half
    hgemm<1, 1><<<dim3(DFF / 256, SEQ / 128), 256, SM_HG>>>(
        xnh, w1h, b1, nullptr, ffh, DMODEL, DFF, DFF);

    // 7. out += ff @ W2 + b2
    hgemm<2, 0><<<dim3(DMODEL / 256, SEQ / 128), 256, SM_HG>>>(
        ffh, w2h, b2, out, nullptr, DFF, DMODEL, DMODEL);
}

// round 15
// speedup vs baseline: 1.1779x; 1.1779x over previous
#include <cuda_runtime.h>
#include <cuda_fp16.h>
#include <math.h>
#include <stdint.h>

#define SEQ 2048
#define DMODEL 2048
#define NH 16
#define DH 128
#define DFF 8192
#define BOTTLE 1088   /* BACKGROUND_LEN + STYLE_VECS_LEN */
#define BG 1024       /* BACKGROUND_LEN */

// -------- scratch (no allocations allowed) --------
__device__ __half g_xnh[(size_t)SEQ * DMODEL];
__device__ __half g_qkvh[(size_t)SEQ * 3 * DMODEL];
__device__ __half g_atth[(size_t)SEQ * DMODEL];
__device__ __half g_ffh[(size_t)SEQ * DFF];
// half weights, NATURAL [K, N] layouts (qkv fused along N)
__device__ __half g_wqkvh[(size_t)DMODEL * 3 * DMODEL];
__device__ __half g_woh[(size_t)DMODEL * DMODEL];
__device__ __half g_w1h[(size_t)DMODEL * DFF];
__device__ __half g_w2h[(size_t)DFF * DMODEL];

// -------- fp16 mma + ldmatrix --------
__device__ __forceinline__ void mma_f16(float c[4], const uint32_t a[4], const uint32_t b0,
                                        const uint32_t b1) {
    asm volatile(
        "mma.sync.aligned.m16n8k16.row.col.f32.f16.f16.f32 "
        "{%0,%1,%2,%3}, {%4,%5,%6,%7}, {%8,%9}, {%0,%1,%2,%3};\n"
        : "+f"(c[0]), "+f"(c[1]), "+f"(c[2]), "+f"(c[3])
        : "r"(a[0]), "r"(a[1]), "r"(a[2]), "r"(a[3]), "r"(b0), "r"(b1));
}
__device__ __forceinline__ void ldsm4(uint32_t* r, uint32_t addr) {
    asm volatile("ldmatrix.sync.aligned.m8n8.x4.shared.b16 {%0,%1,%2,%3}, [%4];"
                 : "=r"(r[0]), "=r"(r[1]), "=r"(r[2]), "=r"(r[3]) : "r"(addr));
}
__device__ __forceinline__ void ldsm4t(uint32_t* r, uint32_t addr) {
    asm volatile("ldmatrix.sync.aligned.m8n8.x4.trans.shared.b16 {%0,%1,%2,%3}, [%4];"
                 : "=r"(r[0]), "=r"(r[1]), "=r"(r[2]), "=r"(r[3]) : "r"(addr));
}
// pack two fp32 -> one fp16x2 register (lo = a, hi = b)
__device__ __forceinline__ uint32_t packh2(float a, float b) {
    uint32_t r;
    asm("cvt.rn.f16x2.f32 %0, %2, %1;" : "=r"(r) : "f"(a), "f"(b));
    return r;
}

// -------- cp.async helpers --------
__device__ __forceinline__ void cp16(uint32_t s, const void* g) {
    asm volatile("cp.async.cg.shared.global [%0], [%1], 16;" :: "r"(s), "l"(g));
}
__device__ __forceinline__ void cp_commit() { asm volatile("cp.async.commit_group;"); }
template <int N> __device__ __forceinline__ void cp_wait() {
    asm volatile("cp.async.wait_group %0;" :: "n"(N));
}

// -------- reductions --------
__device__ __forceinline__ float blockReduceSum(float val) {
    __shared__ float sh[8];
    __shared__ float res;
    int lane = threadIdx.x & 31, w = threadIdx.x >> 5;
    #pragma unroll
    for (int o = 16; o > 0; o >>= 1) val += __shfl_xor_sync(0xffffffffu, val, o);
    if (lane == 0) sh[w] = val;
    __syncthreads();
    if (threadIdx.x == 0) {
        float s = 0.f;
        #pragma unroll
        for (int i = 0; i < 8; i++) s += sh[i];
        res = s;
    }
    __syncthreads();
    float r = res;
    __syncthreads();
    return r;
}

// -------- streaming fp32 -> fp16 convert, 4 float4 per thread (MLP=4) --------
// N4 = row length in float4 units, power of two; sh = log2(N4).
__global__ void cvt_h_kernel(const float4* __restrict__ in, __half* __restrict__ out,
                             int sh, int ldo, int off, int total4) {
    int i0 = blockIdx.x * (blockDim.x * 4) + threadIdx.x;
    float4 v[4];
    int idx[4];
    #pragma unroll
    for (int j = 0; j < 4; j++) {
        idx[j] = i0 + j * blockDim.x;
        if (idx[j] < total4) v[j] = in[idx[j]];
    }
    #pragma unroll
    for (int j = 0; j < 4; j++) {
        if (idx[j] < total4) {
            int row = idx[j] >> sh, c4 = idx[j] & ((1 << sh) - 1);
            uint2 o;
            o.x = packh2(v[j].x, v[j].y);
            o.y = packh2(v[j].z, v[j].w);
            *(uint2*)(out + (size_t)row * ldo + off + c4 * 4) = o;
        }
    }
}

// -------- LayerNorm (half output) --------
__global__ void ln_kernel(const float* __restrict__ x, const float* __restrict__ sc,
                          const float* __restrict__ of, __half* __restrict__ out) {
    int row = blockIdx.x;
    const float* xr = x + (size_t)row * DMODEL;
    __half* o = out + (size_t)row * DMODEL;
    float s = 0.f, s2 = 0.f;
    for (int i = threadIdx.x; i < DMODEL; i += blockDim.x) {
        float v = xr[i];
        s += v; s2 += v * v;
    }
    s  = blockReduceSum(s);
    s2 = blockReduceSum(s2);
    float mean = s / DMODEL;
    float var  = s2 / DMODEL - mean * mean;
    float r = rsqrtf(var + 1e-5f);
    for (int i = threadIdx.x; i < DMODEL; i += blockDim.x)
        o[i] = __float2half_rn(sc[i] * r * (xr[i] - mean) + of[i]);
}

// -------- RoPE on packed half qkv (q at 0, k at DMODEL) --------
__global__ void rope_kernel(__half* __restrict__ qkv) {
    int idx = blockIdx.x * blockDim.x + threadIdx.x;
    if (idx >= SEQ * (DMODEL / 2)) return;
    int t = idx / (DMODEL / 2);
    int r = idx % (DMODEL / 2);
    int h = r / (DH / 2);
    int i = r % (DH / 2);
    float inv = powf(10000.0f, -(float)(2 * i) / (float)DH);
    float ang = (float)t * inv;
    float s, c;
    sincosf(ang, &s, &c);
    size_t base = (size_t)t * (3 * DMODEL) + (size_t)h * DH + 2 * i;
    __half2* qp = (__half2*)(qkv + base);
    float2 q = __half22float2(*qp);
    *qp = __floats2half2_rn(q.x * c - q.y * s, q.y * c + q.x * s);
    __half2* kp = (__half2*)(qkv + base + DMODEL);
    float2 k = __half22float2(*kp);
    *kp = __floats2half2_rn(k.x * c - k.y * s, k.y * c + k.x * s);
}

__device__ __forceinline__ float gelu_f(float x) {
    float x3 = x * x * x;
    return 0.5f * x * (1.0f + tanhf(0.7978845608028654f * (x + 0.044715f * x3)));
}

// ============ FP16 tensor-core GEMM, B in NATURAL [K,N] (trans-ldmatrix) ============
// 128x128 CTA tile, 8 warps 64x32, BK=32, 4-stage cp.async, 2 CTAs/SM.
// EPI 0: v = acc   EPI 1: v = gelu(acc + bias[n])   EPI 2: v = C[idx] + acc + bias[n]
// OUTH: write half to Ch.
template <int EPI, int OUTH>
__global__ __launch_bounds__(256, 2)
void hgemm(const __half* __restrict__ A, const __half* __restrict__ B,
           const float* __restrict__ bias, float* __restrict__ C,
           __half* __restrict__ Ch, int K, int ldb, int ldc) {
    constexpr int S = 4, BK = 32;
    constexpr int LDA = 40;                  // A smem row halves (pad 8)
    constexpr int LDB = 136;                 // B smem row halves (pad 8)
    constexpr int ASTAGE = 128 * LDA;        // 5120 halves
    constexpr int BSTAGE = BK * LDB;         // 4352 halves

    extern __shared__ __half smh[];
    __half* Asm = smh;
    __half* Bsm = smh + S * ASTAGE;

    int t = threadIdx.x;
    int m0 = blockIdx.y * 128, n0 = blockIdx.x * 128;
    int lane = t & 31, warp = t >> 5;
    int wm = (warp >> 2) * 64;
    int wn = (warp & 3) * 32;
    int gid = lane >> 2, t4 = lane & 3;

    float acc[4][4][4];
    #pragma unroll
    for (int f = 0; f < 4; f++)
        #pragma unroll
        for (int g = 0; g < 4; g++)
            #pragma unroll
            for (int e = 0; e < 4; e++) acc[f][g][e] = 0.f;

    uint32_t aBase = (uint32_t)__cvta_generic_to_shared(Asm);
    uint32_t bBase = (uint32_t)__cvta_generic_to_shared(Bsm);

    int nt = K / BK;

    // A stage: 128 rows x 32 halves = 512 x 8-half chunks (16B each)
    // B stage: 32 rows x 128 halves = 512 x 8-half chunks
    auto load_stage = [&](int s, int kt) {
        int k0 = kt * BK;
        uint32_t as = aBase + s * ASTAGE * 2;
        uint32_t bs = bBase + s * BSTAGE * 2;
        #pragma unroll
        for (int i = 0; i < 2; i++) {
            int cid = t + i * 256;
            int row = cid >> 2, c = (cid & 3) * 8;
            cp16(as + (row * LDA + c) * 2, A + (size_t)(m0 + row) * K + k0 + c);
        }
        #pragma unroll
        for (int i = 0; i < 2; i++) {
            int cid = t + i * 256;
            int row = cid >> 4, c = (cid & 15) * 8;
            cp16(bs + (row * LDB + c) * 2, B + (size_t)(k0 + row) * ldb + n0 + c);
        }
    };

    #pragma unroll
    for (int s = 0; s < S - 1; s++) {
        if (s < nt) load_stage(s, s);
        cp_commit();
    }

    int lrow = (lane & 7) + ((lane >> 3) & 1) * 8;   // A ldsm row
    int lcol = (lane >> 4) * 8;                      // A ldsm k-offset
    int vrow = lane & 15, vcol = (lane >> 4) * 8;    // B trans-ldsm row/col

    for (int kt = 0; kt < nt; kt++) {
        cp_wait<S - 2>();
        __syncthreads();
        int nx = kt + S - 1;
        if (nx < nt) load_stage(nx & (S - 1), nx);
        cp_commit();

        uint32_t as = aBase + (kt & (S - 1)) * ASTAGE * 2;
        uint32_t bs = bBase + (kt & (S - 1)) * BSTAGE * 2;

        #pragma unroll
        for (int kk = 0; kk < BK; kk += 16) {
            uint32_t af[4][4];
            #pragma unroll
            for (int f = 0; f < 4; f++)
                ldsm4(af[f], as + ((wm + f * 16 + lrow) * LDA + kk + lcol) * 2);
            uint32_t bf[2][4];
            #pragma unroll
            for (int g2 = 0; g2 < 2; g2++)
                ldsm4t(bf[g2], bs + ((kk + vrow) * LDB + wn + g2 * 16 + vcol) * 2);
            #pragma unroll
            for (int f = 0; f < 4; f++) {
                mma_f16(acc[f][0], af[f], bf[0][0], bf[0][1]);
                mma_f16(acc[f][1], af[f], bf[0][2], bf[0][3]);
                mma_f16(acc[f][2], af[f], bf[1][0], bf[1][1]);
                mma_f16(acc[f][3], af[f], bf[1][2], bf[1][3]);
            }
        }
    }

    #pragma unroll
    for (int f = 0; f < 4; f++) {
        #pragma unroll
        for (int g = 0; g < 4; g++) {
            #pragma unroll
            for (int half = 0; half < 2; half++) {
                int m = m0 + wm + f * 16 + gid + half * 8;
                int n = n0 + wn + g * 8 + 2 * t4;
                float v0 = acc[f][g][half * 2 + 0];
                float v1 = acc[f][g][half * 2 + 1];
                size_t idx = (size_t)m * ldc + n;
                if (EPI == 1) {
                    v0 = gelu_f(v0 + bias[n]);
                    v1 = gelu_f(v1 + bias[n + 1]);
                } else if (EPI == 2) {
                    v0 = C[idx]     + v0 + bias[n];
                    v1 = C[idx + 1] + v1 + bias[n + 1];
                }
                if (OUTH) {
                    *(uint32_t*)(Ch + idx) = packh2(v0, v1);
                } else {
                    C[idx]     = v0;
                    C[idx + 1] = v1;
                }
            }
        }
    }
}

// ============ FP16 flash attention (m16n8k16 mma, ldmatrix, online softmax) ============
__global__ void __launch_bounds__(256, 1)
flash_kernel(const __half* __restrict__ qkv, const float* __restrict__ bias,
             __half* __restrict__ att) {
    constexpr int LD = 3 * DMODEL;
    constexpr int STR = 136;
    extern __shared__ __half smh[];
    __half* Qs = smh;
    __half* Ks = smh + 128 * STR;
    __half* Vs = smh + 2 * 128 * STR;
    uint32_t qB = (uint32_t)__cvta_generic_to_shared(Qs);
    uint32_t kB = (uint32_t)__cvta_generic_to_shared(Ks);
    uint32_t vB = (uint32_t)__cvta_generic_to_shared(Vs);

    int mb = blockIdx.x, h = blockIdx.y;
    int m0 = mb * 128;
    int t = threadIdx.x, lane = t & 31, warp = t >> 5;
    int gid = lane >> 2, t4 = lane & 3;
    int wrow = warp * 16;

    const __half* kbase = qkv + DMODEL + h * DH;
    const __half* vbase = qkv + 2 * DMODEL + h * DH;

    int lr = t >> 1, lc = (t & 1) * 64;

    int it0 = (m0 >= 1152) ? 8 : 0;
    {
        const __half* g = qkv + (size_t)(m0 + lr) * LD + h * DH + lc;
        uint32_t s = qB + (lr * STR + lc) * 2;
        #pragma unroll
        for (int i = 0; i < 8; i++) cp16(s + i * 16, g + i * 8);
    }
    {
        const __half* g = kbase + (size_t)(it0 * 128 + lr) * LD + lc;
        uint32_t s = kB + (lr * STR + lc) * 2;
        #pragma unroll
        for (int i = 0; i < 8; i++) cp16(s + i * 16, g + i * 8);
    }
    cp_commit();
    cp_wait<0>();
    __syncthreads();

    float o[16][4];
    #pragma unroll
    for (int g = 0; g < 16; g++) { o[g][0] = o[g][1] = o[g][2] = o[g][3] = 0.f; }
    float mrow0 = -INFINITY, mrow1 = -INFINITY;
    float lsum0 = 0.f, lsum1 = 0.f;

    const float scale = 0.08838834764831845f;
    int me0 = m0 + wrow + gid;
    int me1 = me0 + 8;

    int lrow = (lane & 7) + ((lane >> 3) & 1) * 8;
    int lcol = (lane >> 4) * 8;
    int vrow = lane & 15, vcol = (lane >> 4) * 8;

    for (int it = it0; it <= mb; it++) {
        int n0 = it * 128;

        {
            const __half* g = vbase + (size_t)(n0 + lr) * LD + lc;
            uint32_t s = vB + (lr * STR + lc) * 2;
            #pragma unroll
            for (int i = 0; i < 8; i++) cp16(s + i * 16, g + i * 8);
            cp_commit();
        }

        float s[16][4];
        #pragma unroll
        for (int g = 0; g < 16; g++) s[g][0] = s[g][1] = s[g][2] = s[g][3] = 0.f;

        #pragma unroll
        for (int kk = 0; kk < DH; kk += 16) {
            uint32_t af[4];
            ldsm4(af, qB + ((wrow + lrow) * STR + kk + lcol) * 2);
            #pragma unroll
            for (int g2 = 0; g2 < 8; g2++) {
                uint32_t bf[4];
                ldsm4(bf, kB + ((g2 * 16 + lrow) * STR + kk + lcol) * 2);
                mma_f16(s[2 * g2 + 0], af, bf[0], bf[2]);
                mma_f16(s[2 * g2 + 1], af, bf[1], bf[3]);
            }
        }
        __syncthreads();

        if (it < mb) {
            const __half* g = kbase + (size_t)(n0 + 128 + lr) * LD + lc;
            uint32_t sa = kB + (lr * STR + lc) * 2;
            #pragma unroll
            for (int i = 0; i < 8; i++) cp16(sa + i * 16, g + i * 8);
        }
        cp_commit();

        float mx0 = -INFINITY, mx1 = -INFINITY;
        const float* bp0 = bias + (size_t)me0 * SEQ + n0 + 2 * t4;
        const float* bp1 = bias + (size_t)me1 * SEQ + n0 + 2 * t4;
        #pragma unroll
        for (int g = 0; g < 16; g++) {
            int nc = n0 + g * 8 + 2 * t4;
            float2 b0 = *(const float2*)(bp0 + g * 8);
            float2 b1 = *(const float2*)(bp1 + g * 8);
            bool a00 = (nc     <= me0) && !((me0 >= BOTTLE) && (nc     < BG));
            bool a01 = (nc + 1 <= me0) && !((me0 >= BOTTLE) && (nc + 1 < BG));
            bool a10 = (nc     <= me1) && !((me1 >= BOTTLE) && (nc     < BG));
            bool a11 = (nc + 1 <= me1) && !((me1 >= BOTTLE) && (nc + 1 < BG));
            s[g][0] = s[g][0] * scale + (a00 ? 0.f : -1e10f) + b0.x;
            s[g][1] = s[g][1] * scale + (a01 ? 0.f : -1e10f) + b0.y;
            s[g][2] = s[g][2] * scale + (a10 ? 0.f : -1e10f) + b1.x;
            s[g][3] = s[g][3] * scale + (a11 ? 0.f : -1e10f) + b1.y;
            mx0 = fmaxf(mx0, fmaxf(s[g][0], s[g][1]));
            mx1 = fmaxf(mx1, fmaxf(s[g][2], s[g][3]));
        }
        mx0 = fmaxf(mx0, __shfl_xor_sync(0xffffffffu, mx0, 1));
        mx0 = fmaxf(mx0, __shfl_xor_sync(0xffffffffu, mx0, 2));
        mx1 = fmaxf(mx1, __shfl_xor_sync(0xffffffffu, mx1, 1));
        mx1 = fmaxf(mx1, __shfl_xor_sync(0xffffffffu, mx1, 2));
        float mn0 = fmaxf(mrow0, mx0), mn1 = fmaxf(mrow1, mx1);
        float al0 = __expf(mrow0 - mn0), al1 = __expf(mrow1 - mn1);
        float rs0 = 0.f, rs1 = 0.f;
        #pragma unroll
        for (int g = 0; g < 16; g++) {
            s[g][0] = __expf(s[g][0] - mn0);
            s[g][1] = __expf(s[g][1] - mn0);
            s[g][2] = __expf(s[g][2] - mn1);
            s[g][3] = __expf(s[g][3] - mn1);
            rs0 += s[g][0] + s[g][1];
            rs1 += s[g][2] + s[g][3];
        }
        lsum0 = lsum0 * al0 + rs0;
        lsum1 = lsum1 * al1 + rs1;
        mrow0 = mn0; mrow1 = mn1;
        #pragma unroll
        for (int g = 0; g < 16; g++) {
            o[g][0] *= al0; o[g][1] *= al0; o[g][2] *= al1; o[g][3] *= al1;
        }

        cp_wait<1>();
        __syncthreads();

        #pragma unroll
        for (int kt = 0; kt < 8; kt++) {
            uint32_t a[4];
            a[0] = packh2(s[2 * kt][0],     s[2 * kt][1]);
            a[1] = packh2(s[2 * kt][2],     s[2 * kt][3]);
            a[2] = packh2(s[2 * kt + 1][0], s[2 * kt + 1][1]);
            a[3] = packh2(s[2 * kt + 1][2], s[2 * kt + 1][3]);
            #pragma unroll
            for (int nf2 = 0; nf2 < 8; nf2++) {
                uint32_t bf[4];
                ldsm4t(bf, vB + ((kt * 16 + vrow) * STR + nf2 * 16 + vcol) * 2);
                mma_f16(o[2 * nf2 + 0], a, bf[0], bf[1]);
                mma_f16(o[2 * nf2 + 1], a, bf[2], bf[3]);
            }
        }
        cp_wait<0>();
        __syncthreads();
    }

    lsum0 += __shfl_xor_sync(0xffffffffu, lsum0, 1);
    lsum0 += __shfl_xor_sync(0xffffffffu, lsum0, 2);
    lsum1 += __shfl_xor_sync(0xffffffffu, lsum1, 1);
    lsum1 += __shfl_xor_sync(0xffffffffu, lsum1, 2);
    float inv0 = 1.f / lsum0, inv1 = 1.f / lsum1;
    __half* o0 = att + (size_t)me0 * DMODEL + h * DH + 2 * t4;
    __half* o1 = att + (size_t)me1 * DMODEL + h * DH + 2 * t4;
    #pragma unroll
    for (int nf = 0; nf < 16; nf++) {
        *(uint32_t*)(o0 + nf * 8) = packh2(o[nf][0] * inv0, o[nf][1] * inv0);
        *(uint32_t*)(o1 + nf * 8) = packh2(o[nf][2] * inv1, o[nf][3] * inv1);
    }
}

extern "C" void kernel_launch(void* const* d_in, const int* in_sizes, int n_in,
                              void* d_out, int out_size) {
    (void)in_sizes; (void)n_in; (void)out_size;
    const float* x         = (const float*)d_in[0];
    const float* attn_bias = (const float*)d_in[1];
    const float* ln_scale  = (const float*)d_in[2];
    const float* ln_offset = (const float*)d_in[3];
    const float* Wq = (const float*)d_in[4];
    const float* Wk = (const float*)d_in[5];
    const float* Wv = (const float*)d_in[6];
    const float* Wo = (const float*)d_in[7];
    const float* W1 = (const float*)d_in[8];
    const float* b1 = (const float*)d_in[9];
    const float* W2 = (const float*)d_in[10];
    const float* b2 = (const float*)d_in[11];
    float* out = (float*)d_out;

    __half *xnh, *qkvh, *atth, *ffh, *wqkvh, *woh, *w1h, *w2h;
    cudaGetSymbolAddress((void**)&xnh,   g_xnh);
    cudaGetSymbolAddress((void**)&qkvh,  g_qkvh);
    cudaGetSymbolAddress((void**)&atth,  g_atth);
    cudaGetSymbolAddress((void**)&ffh,   g_ffh);
    cudaGetSymbolAddress((void**)&wqkvh, g_wqkvh);
    cudaGetSymbolAddress((void**)&woh,   g_woh);
    cudaGetSymbolAddress((void**)&w1h,   g_w1h);
    cudaGetSymbolAddress((void**)&w2h,   g_w2h);

    const int SM_HG = 4 * (128 * 40 + 32 * 136) * 2;   // 75776 B
    const int SM_FA = 3 * 128 * 136 * 2;                // 104448 B
    cudaFuncSetAttribute(hgemm<0, 1>, cudaFuncAttributeMaxDynamicSharedMemorySize, SM_HG);
    cudaFuncSetAttribute(hgemm<0, 0>, cudaFuncAttributeMaxDynamicSharedMemorySize, SM_HG);
    cudaFuncSetAttribute(hgemm<1, 1>, cudaFuncAttributeMaxDynamicSharedMemorySize, SM_HG);
    cudaFuncSetAttribute(hgemm<2, 0>, cudaFuncAttributeMaxDynamicSharedMemorySize, SM_HG);
    cudaFuncSetAttribute(flash_kernel, cudaFuncAttributeMaxDynamicSharedMemorySize, SM_FA);

    // 0. Streaming fp16 conversion of weights (natural [K,N] layout; qkv fused along N)
    {
        int thr = 256, per = thr * 4;
        int n4a = DMODEL * DMODEL / 4;
        int n4b = DMODEL * DFF / 4;
        cvt_h_kernel<<<(n4a + per - 1) / per, thr>>>((const float4*)Wq, wqkvh, 9,  3 * DMODEL, 0,          n4a);
        cvt_h_kernel<<<(n4a + per - 1) / per, thr>>>((const float4*)Wk, wqkvh, 9,  3 * DMODEL, DMODEL,     n4a);
        cvt_h_kernel<<<(n4a + per - 1) / per, thr>>>((const float4*)Wv, wqkvh, 9,  3 * DMODEL, 2 * DMODEL, n4a);
        cvt_h_kernel<<<(n4a + per - 1) / per, thr>>>((const float4*)Wo, woh, 9,  DMODEL, 0, n4a);
        cvt_h_kernel<<<(n4b + per - 1) / per, thr>>>((const float4*)W1, w1h, 11, DFF,    0, n4b);
        cvt_h_kernel<<<(n4b + per - 1) / per, thr>>>((const float4*)W2, w2h, 9,  DMODEL, 0, n4b);
    }

    // 1. LayerNorm -> xn half
    ln_kernel<<<SEQ, 256>>>(x, ln_scale, ln_offset, xnh);

    // 2. Fused QKV projection -> qkv half [SEQ, 6144]
    hgemm<0, 1><<<dim3(3 * DMODEL / 128, SEQ / 128), 256, SM_HG>>>(
        xnh, wqkvh, nullptr, nullptr, qkvh, DMODEL, 3 * DMODEL, 3 * DMODEL);

    // 3. RoPE (half, in place)
    rope_kernel<<<(SEQ * (DMODEL / 2) + 255) / 256, 256>>>(qkvh);

    // 4. FP16 flash attention -> att half
    flash_kernel<<<dim3(SEQ / 128, NH), 256, SM_FA>>>(qkvh, attn_bias, atth);

    // 5. attn_out = att @ Wo -> d_out (fp32)
    hgemm<0, 0><<<dim3(DMODEL / 128, SEQ / 128), 256, SM_HG>>>(
        atth, woh, nullptr, out, nullptr, DMODEL, DMODEL, DMODEL);

    // 6. ff = gelu(xn @ W1 + b1) -> half
    hgemm<1, 1><<<dim3(DFF / 128, SEQ / 128), 256, SM_HG>>>(
        xnh, w1h, b1, nullptr, ffh, DMODEL, DFF, DFF);

    // 7. out += ff @ W2 + b2
    hgemm<2, 0><<<dim3(DMODEL / 128, SEQ / 128), 256, SM_HG>>>(
        ffh, w2h, b2, out, nullptr, DFF, DMODEL, DMODEL);
}